// round 6
// baseline (speedup 1.0000x reference)
#include <cuda_runtime.h>
#include <cuda_bf16.h>
#include <cstdint>

#define Bsz 4
#define Ssz 2048
#define Dsz 1024
#define Hsz 16
#define DHsz 64

// fp32 scratch (tf32-pre-rounded): Q (x0.125), K in [B,H,S,DH];
// V^T [B,H,DH,S] with key index permuted by pi={0,2,4,6,1,3,5,7} per 8-group.
__device__ float g_Qf[(size_t)Bsz*Hsz*Ssz*DHsz];
__device__ float g_Kf[(size_t)Bsz*Hsz*Ssz*DHsz];
__device__ float g_Vt[(size_t)Bsz*Hsz*DHsz*Ssz];

__device__ __forceinline__ uint32_t smem_u32(const void* p) {
    return (uint32_t)__cvta_generic_to_shared(p);
}
__device__ __forceinline__ void cpa16(uint32_t s, const void* g) {
    asm volatile("cp.async.cg.shared.global [%0], [%1], 16;" :: "r"(s), "l"(g));
}
__device__ __forceinline__ float tf32r(float x) {
    uint32_t r;
    asm("cvt.rna.tf32.f32 %0, %1;" : "=r"(r) : "f"(x));
    return __uint_as_float(r);
}
__device__ __forceinline__ void mma_tf32(float* c, const uint32_t* a, uint32_t b0, uint32_t b1) {
    asm volatile(
        "mma.sync.aligned.m16n8k8.row.col.f32.tf32.tf32.f32 "
        "{%0,%1,%2,%3}, {%4,%5,%6,%7}, {%8,%9}, {%0,%1,%2,%3};"
        : "+f"(c[0]), "+f"(c[1]), "+f"(c[2]), "+f"(c[3])
        : "r"(a[0]), "r"(a[1]), "r"(a[2]), "r"(a[3]), "r"(b0), "r"(b1));
}

// ---------------------------------------------------------------------------
// Kernel A: fused QKV projection -> tf32-rounded fp32 scratch.
// grid (S/64, H, B), 256 threads.
// ---------------------------------------------------------------------------
__global__ __launch_bounds__(256) void qkv_kernel(
    const float* __restrict__ x,
    const float* __restrict__ Wq, const float* __restrict__ bq,
    const float* __restrict__ Wk, const float* __restrict__ bk,
    const float* __restrict__ Wv, const float* __restrict__ bv)
{
    __shared__ float xs[64 * 64];
    __shared__ float wt[64 * 65];   // padded: conflict-free transpose

    const int s0  = blockIdx.x * 64;
    const int h   = blockIdx.y;
    const int b   = blockIdx.z;
    const int tid = threadIdx.x;

    const float4* xg  = reinterpret_cast<const float4*>(x);
    float4*       xs4 = reinterpret_cast<float4*>(xs);
    #pragma unroll
    for (int j = tid; j < 64 * 16; j += 256) {
        int r = j >> 4, c = j & 15;
        xs4[j] = xg[((size_t)(b * Ssz + s0 + r) * Dsz + h * DHsz) / 4 + c];
    }

    const float* Ws[3]   = {Wq, Wk, Wv};
    const float* bvec[3] = {bq, bk, bv};

    const int e  = tid & 63;
    const int rg = tid >> 6;
    const size_t bh = (size_t)b * Hsz + h;

    #pragma unroll
    for (int m = 0; m < 3; m++) {
        __syncthreads();
        const float* W = Ws[m] + h * DHsz * DHsz;
        for (int i = tid; i < 64 * 64; i += 256) {
            int eo = i >> 6, d = i & 63;
            wt[d * 65 + eo] = W[i];
        }
        __syncthreads();

        float wcol[64];
        #pragma unroll
        for (int d = 0; d < 64; d++) wcol[d] = wt[d * 65 + e];
        const float bias = bvec[m][h * DHsz + e];

        if (m < 2) {
            float* O = (m == 0 ? g_Qf : g_Kf) + (bh * Ssz + s0) * DHsz;
            const float scale = (m == 0) ? 0.125f : 1.0f;
            #pragma unroll
            for (int ri = 0; ri < 16; ri++) {
                int r = rg * 16 + ri;
                float a0 = 0.f, a1 = 0.f, a2 = 0.f, a3 = 0.f;
                const float4* xr = xs4 + r * 16;
                #pragma unroll
                for (int dc = 0; dc < 16; dc++) {
                    float4 xv = xr[dc];
                    a0 += xv.x * wcol[4*dc];
                    a1 += xv.y * wcol[4*dc+1];
                    a2 += xv.z * wcol[4*dc+2];
                    a3 += xv.w * wcol[4*dc+3];
                }
                float acc = bias + ((a0 + a1) + (a2 + a3));
                O[r * DHsz + e] = tf32r(acc * scale);
            }
        } else {
            float accs[16];
            #pragma unroll
            for (int ri = 0; ri < 16; ri++) {
                int r = rg * 16 + ri;
                float a0 = 0.f, a1 = 0.f, a2 = 0.f, a3 = 0.f;
                const float4* xr = xs4 + r * 16;
                #pragma unroll
                for (int dc = 0; dc < 16; dc++) {
                    float4 xv = xr[dc];
                    a0 += xv.x * wcol[4*dc];
                    a1 += xv.y * wcol[4*dc+1];
                    a2 += xv.z * wcol[4*dc+2];
                    a3 += xv.w * wcol[4*dc+3];
                }
                accs[ri] = tf32r(bias + ((a0 + a1) + (a2 + a3)));
            }
            // V^T: [B,H,DH,S]; this thread owns dh=e, seq [s0+rg*16, +16).
            // Permute key index within each 8-group: pos u holds key pi(u).
            const int pi[8] = {0, 2, 4, 6, 1, 3, 5, 7};
            float tmp[16];
            #pragma unroll
            for (int a = 0; a < 2; a++)
                #pragma unroll
                for (int u = 0; u < 8; u++)
                    tmp[8*a + u] = accs[8*a + pi[u]];
            float4* dst = reinterpret_cast<float4*>(
                g_Vt + (bh * DHsz + e) * Ssz + s0 + rg * 16);
            #pragma unroll
            for (int i = 0; i < 4; i++)
                dst[i] = make_float4(tmp[4*i], tmp[4*i+1], tmp[4*i+2], tmp[4*i+3]);
        }
    }
}

// ---------------------------------------------------------------------------
// Kernel B: FA2-style attention, mma.sync m16n8k8 tf32, register-resident P.
// grid (S/128, H, B), 256 threads (8 warps x 16 query rows each), 2 CTAs/SM.
// SMEM (floats): K[2][64*68] | V[2][64*68]  (69.6 KB)
// ---------------------------------------------------------------------------
#define KST 68
#define SMEM_FLOATS (4 * 64 * KST)

__global__ __launch_bounds__(256, 2) void attn_kernel(float* __restrict__ out)
{
    extern __shared__ float sm[];

    const int tid  = threadIdx.x;
    const int wid  = tid >> 5;
    const int lane = tid & 31;
    const int g    = lane >> 2;
    const int tq   = lane & 3;

    const int q0 = blockIdx.x * 128;
    const int h  = blockIdx.y;
    const int b  = blockIdx.z;
    const size_t bh = (size_t)b * Hsz + h;

    const float* Kg = g_Kf + bh * Ssz * DHsz;
    const float* Vg = g_Vt + bh * DHsz * Ssz;

    float* sKf[2] = {sm, sm + 64 * KST};
    float* sVf[2] = {sm + 2 * 64 * KST, sm + 3 * 64 * KST};
    const uint32_t sKa[2] = {smem_u32(sKf[0]), smem_u32(sKf[1])};
    const uint32_t sVa[2] = {smem_u32(sVf[0]), smem_u32(sVf[1])};

    // cp.async slots: 1024 16B-chunks per K/V tile, 256 threads -> 4 each
    int ldrow[4], ldch[4];
    #pragma unroll
    for (int i = 0; i < 4; i++) {
        int idx = tid + i * 256;
        ldrow[i] = idx >> 4;
        ldch[i]  = idx & 15;
    }

    // ---- issue tile 0 ----
    #pragma unroll
    for (int i = 0; i < 4; i++) {
        cpa16(sKa[0] + (ldrow[i] * KST + ldch[i] * 4) * 4,
              Kg + (size_t)ldrow[i] * DHsz + ldch[i] * 4);
        cpa16(sVa[0] + (ldrow[i] * KST + ldch[i] * 4) * 4,
              Vg + (size_t)ldrow[i] * Ssz + ldch[i] * 4);
    }
    asm volatile("cp.async.commit_group;" ::: "memory");

    // ---- persistent Q A-fragments: warp owns rows [q0+16*wid, +16) ----
    uint32_t aq[8][4];
    {
        const float* Qg = g_Qf + (bh * Ssz + q0 + wid * 16) * DHsz;
        #pragma unroll
        for (int kj = 0; kj < 8; kj++) {
            int c = kj * 8 + tq;
            aq[kj][0] = __float_as_uint(Qg[g       * DHsz + c]);
            aq[kj][1] = __float_as_uint(Qg[(g + 8) * DHsz + c]);
            aq[kj][2] = __float_as_uint(Qg[g       * DHsz + c + 4]);
            aq[kj][3] = __float_as_uint(Qg[(g + 8) * DHsz + c + 4]);
        }
    }

    float oc[8][4];
    #pragma unroll
    for (int n = 0; n < 8; n++)
        #pragma unroll
        for (int i = 0; i < 4; i++) oc[n][i] = 0.f;
    float lsum[2] = {0.f, 0.f};

    #pragma unroll 1
    for (int j = 0; j < 32; j++) {
        const int buf = j & 1;
        __syncthreads();
        if (j + 1 < 32) {
            const int nb = (j + 1) & 1;
            const int t0 = (j + 1) * 64;
            #pragma unroll
            for (int i = 0; i < 4; i++) {
                cpa16(sKa[nb] + (ldrow[i] * KST + ldch[i] * 4) * 4,
                      Kg + (size_t)(t0 + ldrow[i]) * DHsz + ldch[i] * 4);
                cpa16(sVa[nb] + (ldrow[i] * KST + ldch[i] * 4) * 4,
                      Vg + (size_t)ldrow[i] * Ssz + t0 + ldch[i] * 4);
            }
        }
        asm volatile("cp.async.commit_group;" ::: "memory");
        asm volatile("cp.async.wait_group 1;" ::: "memory");
        __syncthreads();

        const float* Kb = sKf[buf];
        const float* Vb = sVf[buf];

        // Fused per n-tile: GEMM1 -> exp -> GEMM2 k-chunk (register P)
        #pragma unroll
        for (int ni = 0; ni < 8; ni++) {
            float sc[4] = {0, 0, 0, 0};
            const float* krow = Kb + (8 * ni + g) * KST;
            #pragma unroll
            for (int kj = 0; kj < 8; kj++) {
                uint32_t b0 = __float_as_uint(krow[8 * kj + tq]);
                uint32_t b1 = __float_as_uint(krow[8 * kj + tq + 4]);
                mma_tf32(sc, aq[kj], b0, b1);
            }
            // softmax -> A-frag in registers (C layout -> A layout via V perm)
            float e0 = tf32r(__expf(sc[0]));
            float e1 = tf32r(__expf(sc[1]));
            float e2 = tf32r(__expf(sc[2]));
            float e3 = tf32r(__expf(sc[3]));
            lsum[0] += e0 + e1;   // row g
            lsum[1] += e2 + e3;   // row g+8
            uint32_t pa[4];
            pa[0] = __float_as_uint(e0);
            pa[1] = __float_as_uint(e2);
            pa[2] = __float_as_uint(e1);
            pa[3] = __float_as_uint(e3);
            // GEMM2: O[:, vn] += P[:, chunk ni] @ V
            #pragma unroll
            for (int vn = 0; vn < 8; vn++) {
                const float* vrow = Vb + (8 * vn + g) * KST;
                uint32_t b0 = __float_as_uint(vrow[8 * ni + tq]);
                uint32_t b1 = __float_as_uint(vrow[8 * ni + tq + 4]);
                mma_tf32(oc[vn], pa, b0, b1);
            }
        }
    }

    // ---- reduce row sums across quads, normalize, store ----
    float inv[2];
    #pragma unroll
    for (int hh = 0; hh < 2; hh++) {
        float v = lsum[hh];
        v += __shfl_xor_sync(0xffffffff, v, 1);
        v += __shfl_xor_sync(0xffffffff, v, 2);
        inv[hh] = 1.f / v;
    }

    const int r0 = q0 + wid * 16 + g;
    #pragma unroll
    for (int n = 0; n < 8; n++) {
        int col = h * DHsz + n * 8 + tq * 2;
        float2* p0 = reinterpret_cast<float2*>(out + (size_t)(b * Ssz + r0) * Dsz + col);
        float2* p1 = reinterpret_cast<float2*>(out + (size_t)(b * Ssz + r0 + 8) * Dsz + col);
        *p0 = make_float2(oc[n][0] * inv[0], oc[n][1] * inv[0]);
        *p1 = make_float2(oc[n][2] * inv[1], oc[n][3] * inv[1]);
    }
}

extern "C" void kernel_launch(void* const* d_in, const int* in_sizes, int n_in,
                              void* d_out, int out_size)
{
    const float* seqs = (const float*)d_in[0];
    const float* Wq   = (const float*)d_in[1];
    const float* bq   = (const float*)d_in[2];
    const float* Wk   = (const float*)d_in[3];
    const float* bk   = (const float*)d_in[4];
    const float* Wv   = (const float*)d_in[5];
    const float* bv   = (const float*)d_in[6];
    float* out = (float*)d_out;

    cudaFuncSetAttribute(attn_kernel, cudaFuncAttributeMaxDynamicSharedMemorySize,
                         SMEM_FLOATS * (int)sizeof(float));

    dim3 gridQ(Ssz / 64, Hsz, Bsz);
    qkv_kernel<<<gridQ, 256>>>(seqs, Wq, bq, Wk, bk, Wv, bv);

    dim3 gridA(Ssz / 128, Hsz, Bsz);
    attn_kernel<<<gridA, 256, SMEM_FLOATS * sizeof(float)>>>(out);
}

// round 7
// speedup vs baseline: 2.5933x; 2.5933x over previous
#include <cuda_runtime.h>
#include <cuda_fp16.h>
#include <cstdint>

#define Bsz 4
#define Ssz 2048
#define Dsz 1024
#define Hsz 16
#define DHsz 64

// fp16 scratch: Q (pre-scaled x0.125) and K in [B,H,S,DH]; V^T in [B,H,DH,S]
__device__ __half g_Qh[(size_t)Bsz*Hsz*Ssz*DHsz];
__device__ __half g_Kh[(size_t)Bsz*Hsz*Ssz*DHsz];
__device__ __half g_Vh[(size_t)Bsz*Hsz*DHsz*Ssz];

__device__ __forceinline__ uint32_t smem_u32(const void* p) {
    return (uint32_t)__cvta_generic_to_shared(p);
}
__device__ __forceinline__ void cpa16(uint32_t s, const void* g) {
    asm volatile("cp.async.cg.shared.global [%0], [%1], 16;" :: "r"(s), "l"(g));
}
__device__ __forceinline__ void mma_f16(float* c, const uint32_t* a, uint32_t b0, uint32_t b1) {
    asm volatile(
        "mma.sync.aligned.m16n8k16.row.col.f32.f16.f16.f32 "
        "{%0,%1,%2,%3}, {%4,%5,%6,%7}, {%8,%9}, {%0,%1,%2,%3};"
        : "+f"(c[0]), "+f"(c[1]), "+f"(c[2]), "+f"(c[3])
        : "r"(a[0]), "r"(a[1]), "r"(a[2]), "r"(a[3]), "r"(b0), "r"(b1));
}
__device__ __forceinline__ uint32_t packh2(float a, float b) {
    __half2 t = __floats2half2_rn(a, b);
    return *reinterpret_cast<uint32_t*>(&t);
}

// ---------------------------------------------------------------------------
// Kernel A: fused QKV projection on fp16 mma. grid (S/128, H, B), 128 thr.
// SMEM halves: xh[128*72] | wh[3][64*72] | vst[64*136]
// ---------------------------------------------------------------------------
#define XST 72
#define VST 136
#define QK_OFF_X 0
#define QK_OFF_W (128 * XST)
#define QK_OFF_VS (QK_OFF_W + 3 * 64 * XST)
#define QK_SMEM_HALVES (QK_OFF_VS + 64 * VST)

__global__ __launch_bounds__(128, 2) void qkv_kernel(
    const float* __restrict__ x,
    const float* __restrict__ Wq, const float* __restrict__ bq,
    const float* __restrict__ Wk, const float* __restrict__ bk,
    const float* __restrict__ Wv, const float* __restrict__ bv)
{
    extern __shared__ __half smh[];
    __half* xh  = smh + QK_OFF_X;
    __half* vst = smh + QK_OFF_VS;

    const int s0  = blockIdx.x * 128;
    const int h   = blockIdx.y;
    const int b   = blockIdx.z;
    const int tid = threadIdx.x;
    const int wid = tid >> 5;
    const int lane = tid & 31;
    const int g   = lane >> 2;
    const int tq  = lane & 3;
    const size_t bh = (size_t)b * Hsz + h;

    // load x tile [128 rows x 64 d] fp32 -> fp16 smem (stride 72)
    {
        const float4* xg = reinterpret_cast<const float4*>(x)
                         + ((size_t)(b * Ssz + s0) * Dsz + h * DHsz) / 4;
        #pragma unroll
        for (int i = 0; i < 16; i++) {
            int idx = tid + i * 128;            // 2048 float4 chunks
            int r = idx >> 4, c = idx & 15;
            float4 v = xg[r * (Dsz / 4) + c];
            __half2* d = reinterpret_cast<__half2*>(xh + r * XST + c * 4);
            d[0] = __floats2half2_rn(v.x, v.y);
            d[1] = __floats2half2_rn(v.z, v.w);
        }
    }
    // load W tiles [64 e x 64 d] fp32 -> fp16 smem
    const float* Ws[3] = {Wq, Wk, Wv};
    #pragma unroll
    for (int m = 0; m < 3; m++) {
        const float4* wg = reinterpret_cast<const float4*>(Ws[m] + (size_t)h * DHsz * DHsz);
        __half* wh = smh + QK_OFF_W + m * 64 * XST;
        #pragma unroll
        for (int i = 0; i < 8; i++) {
            int idx = tid + i * 128;            // 1024 float4 chunks
            int r = idx >> 4, c = idx & 15;
            float4 v = wg[idx];
            __half2* d = reinterpret_cast<__half2*>(wh + r * XST + c * 4);
            d[0] = __floats2half2_rn(v.x, v.y);
            d[1] = __floats2half2_rn(v.z, v.w);
        }
    }
    __syncthreads();

    // x A-fragments: warp owns 32 rows (m=2 x m16)
    uint32_t ax[2][4][4];
    {
        const __half* xw = xh + (wid * 32) * XST;
        #pragma unroll
        for (int m = 0; m < 2; m++)
            #pragma unroll
            for (int kc = 0; kc < 4; kc++) {
                const __half* r0 = xw + (m * 16 + g) * XST + 16 * kc + 2 * tq;
                ax[m][kc][0] = *(const uint32_t*)(r0);
                ax[m][kc][1] = *(const uint32_t*)(r0 + 8 * XST);
                ax[m][kc][2] = *(const uint32_t*)(r0 + 8);
                ax[m][kc][3] = *(const uint32_t*)(r0 + 8 * XST + 8);
            }
    }

    const float* bvec[3] = {bq, bk, bv};
    #pragma unroll
    for (int mm = 0; mm < 3; mm++) {
        const __half* wh = smh + QK_OFF_W + mm * 64 * XST;
        float sc[2][8][4];
        #pragma unroll
        for (int vn = 0; vn < 8; vn++) {
            float2 bb = *reinterpret_cast<const float2*>(
                bvec[mm] + h * DHsz + 8 * vn + 2 * tq);
            #pragma unroll
            for (int m = 0; m < 2; m++) {
                sc[m][vn][0] = bb.x; sc[m][vn][1] = bb.y;
                sc[m][vn][2] = bb.x; sc[m][vn][3] = bb.y;
            }
        }
        #pragma unroll
        for (int vn = 0; vn < 8; vn++) {
            const __half* wrow = wh + (8 * vn + g) * XST;
            #pragma unroll
            for (int kc = 0; kc < 4; kc++) {
                uint32_t b0 = *(const uint32_t*)(wrow + 16 * kc + 2 * tq);
                uint32_t b1 = *(const uint32_t*)(wrow + 16 * kc + 2 * tq + 8);
                mma_f16(sc[0][vn], ax[0][kc], b0, b1);
                mma_f16(sc[1][vn], ax[1][kc], b0, b1);
            }
        }

        if (mm < 2) {
            __half* O = (mm == 0 ? g_Qh : g_Kh) + (bh * Ssz + s0 + wid * 32) * DHsz;
            const float scl = (mm == 0) ? 0.125f : 1.0f;
            #pragma unroll
            for (int m = 0; m < 2; m++)
                #pragma unroll
                for (int vn = 0; vn < 8; vn++) {
                    int col = 8 * vn + 2 * tq;
                    *(uint32_t*)(O + (m * 16 + g) * DHsz + col) =
                        packh2(sc[m][vn][0] * scl, sc[m][vn][1] * scl);
                    *(uint32_t*)(O + (m * 16 + g + 8) * DHsz + col) =
                        packh2(sc[m][vn][2] * scl, sc[m][vn][3] * scl);
                }
        } else {
            // stage V transposed in smem: vst[e][s_local]
            #pragma unroll
            for (int m = 0; m < 2; m++)
                #pragma unroll
                for (int vn = 0; vn < 8; vn++) {
                    int e = 8 * vn + 2 * tq;
                    int s = wid * 32 + m * 16 + g;
                    vst[e * VST + s]           = __float2half_rn(sc[m][vn][0]);
                    vst[(e + 1) * VST + s]     = __float2half_rn(sc[m][vn][1]);
                    vst[e * VST + s + 8]       = __float2half_rn(sc[m][vn][2]);
                    vst[(e + 1) * VST + s + 8] = __float2half_rn(sc[m][vn][3]);
                }
            __syncthreads();
            // coop store vst -> g_Vh rows (coalesced 16B)
            #pragma unroll
            for (int i = 0; i < 8; i++) {
                int idx = tid + i * 128;        // 1024 chunks of 8 halves
                int dh = idx >> 4, c = idx & 15;
                *reinterpret_cast<uint4*>(g_Vh + (bh * DHsz + dh) * Ssz + s0 + c * 8) =
                    *reinterpret_cast<const uint4*>(vst + dh * VST + c * 8);
            }
        }
    }
}

// ---------------------------------------------------------------------------
// Kernel B: FA2 attention on mma.sync m16n8k16 fp16 (f32 accum), register P
// via C-frag == A-frag identity over n-tile pairs. Score shift -3 baked into
// the GEMM1 accumulator init (cancels in normalization; prevents fp16 ovf).
// grid (S/128, H, B), 128 threads (4 warps x 32 rows), 2 CTAs/SM.
// SMEM halves: K[2][128*72] | V[2][64*136]   (71.7 KB)
// ---------------------------------------------------------------------------
#define KSTh 72
#define VSTh 136
#define A_K_HALVES (128 * KSTh)
#define A_V_HALVES (64 * VSTh)
#define A_SMEM_HALVES (2 * A_K_HALVES + 2 * A_V_HALVES)

__global__ __launch_bounds__(128, 2) void attn_kernel(float* __restrict__ out)
{
    extern __shared__ __half smh[];

    const int tid  = threadIdx.x;
    const int wid  = tid >> 5;
    const int lane = tid & 31;
    const int g    = lane >> 2;
    const int tq   = lane & 3;

    const int q0 = blockIdx.x * 128;
    const int h  = blockIdx.y;
    const int b  = blockIdx.z;
    const size_t bh = (size_t)b * Hsz + h;

    const __half* Kg = g_Kh + bh * Ssz * DHsz;
    const __half* Vg = g_Vh + bh * DHsz * Ssz;

    __half* sKh[2] = {smh, smh + A_K_HALVES};
    __half* sVh[2] = {smh + 2 * A_K_HALVES, smh + 2 * A_K_HALVES + A_V_HALVES};
    const uint32_t sKa[2] = {smem_u32(sKh[0]), smem_u32(sKh[1])};
    const uint32_t sVa[2] = {smem_u32(sVh[0]), smem_u32(sVh[1])};

    // cp.async: K tile 128x8 chunks, V tile 64x16 chunks (16B each) -> 16/thr
    int krow[8], kch[8], vrow[8], vch[8];
    #pragma unroll
    for (int i = 0; i < 8; i++) {
        int idx = tid + i * 128;
        krow[i] = idx >> 3;  kch[i] = idx & 7;
        vrow[i] = idx >> 4;  vch[i] = idx & 15;
    }

    // ---- issue tile 0 ----
    #pragma unroll
    for (int i = 0; i < 8; i++) {
        cpa16(sKa[0] + (krow[i] * KSTh + kch[i] * 8) * 2,
              Kg + (size_t)krow[i] * DHsz + kch[i] * 8);
        cpa16(sVa[0] + (vrow[i] * VSTh + vch[i] * 8) * 2,
              Vg + (size_t)vrow[i] * Ssz + vch[i] * 8);
    }
    asm volatile("cp.async.commit_group;" ::: "memory");

    // ---- persistent Q A-fragments ----
    uint32_t aq[2][4][4];
    {
        const __half* Qg = g_Qh + (bh * Ssz + q0 + wid * 32) * DHsz;
        #pragma unroll
        for (int m = 0; m < 2; m++)
            #pragma unroll
            for (int kc = 0; kc < 4; kc++) {
                const __half* r0 = Qg + (m * 16 + g) * DHsz + 16 * kc + 2 * tq;
                aq[m][kc][0] = *(const uint32_t*)(r0);
                aq[m][kc][1] = *(const uint32_t*)(r0 + 8 * DHsz);
                aq[m][kc][2] = *(const uint32_t*)(r0 + 8);
                aq[m][kc][3] = *(const uint32_t*)(r0 + 8 * DHsz + 8);
            }
    }

    float oc[2][8][4];
    #pragma unroll
    for (int m = 0; m < 2; m++)
        #pragma unroll
        for (int n = 0; n < 8; n++)
            #pragma unroll
            for (int i = 0; i < 4; i++) oc[m][n][i] = 0.f;
    float lsum[2][2] = {{0.f, 0.f}, {0.f, 0.f}};

    #pragma unroll 1
    for (int j = 0; j < 16; j++) {
        const int buf = j & 1;
        __syncthreads();
        if (j + 1 < 16) {
            const int nb = (j + 1) & 1;
            const int t0 = (j + 1) * 128;
            #pragma unroll
            for (int i = 0; i < 8; i++) {
                cpa16(sKa[nb] + (krow[i] * KSTh + kch[i] * 8) * 2,
                      Kg + (size_t)(t0 + krow[i]) * DHsz + kch[i] * 8);
                cpa16(sVa[nb] + (vrow[i] * VSTh + vch[i] * 8) * 2,
                      Vg + (size_t)vrow[i] * Ssz + t0 + vch[i] * 8);
            }
        }
        asm volatile("cp.async.commit_group;" ::: "memory");
        asm volatile("cp.async.wait_group 1;" ::: "memory");
        __syncthreads();

        const __half* Kb = sKh[buf];
        const __half* Vb = sVh[buf];

        // u = k16 chunk of keys (pair of 8-wide n-tiles)
        #pragma unroll
        for (int u = 0; u < 8; u++) {
            float sc[2][2][4];   // [pair p][m][4], init -3 (softmax shift)
            #pragma unroll
            for (int p = 0; p < 2; p++)
                #pragma unroll
                for (int m = 0; m < 2; m++)
                    #pragma unroll
                    for (int i = 0; i < 4; i++) sc[p][m][i] = -3.f;

            #pragma unroll
            for (int p = 0; p < 2; p++) {
                const __half* kr = Kb + (16 * u + 8 * p + g) * KSTh + 2 * tq;
                #pragma unroll
                for (int kc = 0; kc < 4; kc++) {
                    uint32_t b0 = *(const uint32_t*)(kr + 16 * kc);
                    uint32_t b1 = *(const uint32_t*)(kr + 16 * kc + 8);
                    mma_f16(sc[p][0], aq[0][kc], b0, b1);
                    mma_f16(sc[p][1], aq[1][kc], b0, b1);
                }
            }

            // exp + pack: C-frags of (2u, 2u+1) -> A-frag of k16 chunk u
            uint32_t pa[2][4];
            #pragma unroll
            for (int m = 0; m < 2; m++) {
                float f0 = __expf(sc[0][m][0]), f1 = __expf(sc[0][m][1]);
                float f2 = __expf(sc[0][m][2]), f3 = __expf(sc[0][m][3]);
                float h0 = __expf(sc[1][m][0]), h1 = __expf(sc[1][m][1]);
                float h2 = __expf(sc[1][m][2]), h3 = __expf(sc[1][m][3]);
                lsum[m][0] += (f0 + f1) + (h0 + h1);   // row g
                lsum[m][1] += (f2 + f3) + (h2 + h3);   // row g+8
                pa[m][0] = packh2(f0, f1);
                pa[m][1] = packh2(f2, f3);
                pa[m][2] = packh2(h0, h1);
                pa[m][3] = packh2(h2, h3);
            }

            // GEMM2: O += P[:, 16u:16u+16] @ V
            #pragma unroll
            for (int vn = 0; vn < 8; vn++) {
                const __half* vr = Vb + (8 * vn + g) * VSTh + 16 * u + 2 * tq;
                uint32_t b0 = *(const uint32_t*)(vr);
                uint32_t b1 = *(const uint32_t*)(vr + 8);
                mma_f16(oc[0][vn], pa[0], b0, b1);
                mma_f16(oc[1][vn], pa[1], b0, b1);
            }
        }
    }

    // ---- reduce row sums across quads, normalize, store ----
    float inv[2][2];
    #pragma unroll
    for (int m = 0; m < 2; m++)
        #pragma unroll
        for (int hh = 0; hh < 2; hh++) {
            float v = lsum[m][hh];
            v += __shfl_xor_sync(0xffffffff, v, 1);
            v += __shfl_xor_sync(0xffffffff, v, 2);
            inv[m][hh] = 1.f / v;
        }

    #pragma unroll
    for (int m = 0; m < 2; m++) {
        int r0 = q0 + wid * 32 + m * 16 + g;
        #pragma unroll
        for (int n = 0; n < 8; n++) {
            int col = h * DHsz + n * 8 + tq * 2;
            float2* p0 = reinterpret_cast<float2*>(out + (size_t)(b * Ssz + r0) * Dsz + col);
            float2* p1 = reinterpret_cast<float2*>(out + (size_t)(b * Ssz + r0 + 8) * Dsz + col);
            *p0 = make_float2(oc[m][n][0] * inv[m][0], oc[m][n][1] * inv[m][0]);
            *p1 = make_float2(oc[m][n][2] * inv[m][1], oc[m][n][3] * inv[m][1]);
        }
    }
}

extern "C" void kernel_launch(void* const* d_in, const int* in_sizes, int n_in,
                              void* d_out, int out_size)
{
    const float* seqs = (const float*)d_in[0];
    const float* Wq   = (const float*)d_in[1];
    const float* bq   = (const float*)d_in[2];
    const float* Wk   = (const float*)d_in[3];
    const float* bk   = (const float*)d_in[4];
    const float* Wv   = (const float*)d_in[5];
    const float* bv   = (const float*)d_in[6];
    float* out = (float*)d_out;

    static int inited = 0;
    cudaFuncSetAttribute(qkv_kernel, cudaFuncAttributeMaxDynamicSharedMemorySize,
                         QK_SMEM_HALVES * (int)sizeof(__half));
    cudaFuncSetAttribute(attn_kernel, cudaFuncAttributeMaxDynamicSharedMemorySize,
                         A_SMEM_HALVES * (int)sizeof(__half));
    (void)inited;

    dim3 gridQ(Ssz / 128, Hsz, Bsz);
    qkv_kernel<<<gridQ, 128, QK_SMEM_HALVES * sizeof(__half)>>>(
        seqs, Wq, bq, Wk, bk, Wv, bv);

    dim3 gridA(Ssz / 128, Hsz, Bsz);
    attn_kernel<<<gridA, 128, A_SMEM_HALVES * sizeof(__half)>>>(out);
}

// round 8
// speedup vs baseline: 3.0642x; 1.1816x over previous
#include <cuda_runtime.h>
#include <cuda_fp16.h>
#include <cstdint>

#define Bsz 4
#define Ssz 2048
#define Dsz 1024
#define Hsz 16
#define DHsz 64

// fp16 scratch: Q (pre-scaled x0.125*log2e) and K in [B,H,S,DH]; V^T in [B,H,DH,S]
__device__ __half g_Qh[(size_t)Bsz*Hsz*Ssz*DHsz];
__device__ __half g_Kh[(size_t)Bsz*Hsz*Ssz*DHsz];
__device__ __half g_Vh[(size_t)Bsz*Hsz*DHsz*Ssz];

__device__ __forceinline__ uint32_t smem_u32(const void* p) {
    return (uint32_t)__cvta_generic_to_shared(p);
}
__device__ __forceinline__ void cpa16(uint32_t s, const void* g) {
    asm volatile("cp.async.cg.shared.global [%0], [%1], 16;" :: "r"(s), "l"(g));
}
__device__ __forceinline__ void mma_f16(float* c, const uint32_t* a, uint32_t b0, uint32_t b1) {
    asm volatile(
        "mma.sync.aligned.m16n8k16.row.col.f32.f16.f16.f32 "
        "{%0,%1,%2,%3}, {%4,%5,%6,%7}, {%8,%9}, {%0,%1,%2,%3};"
        : "+f"(c[0]), "+f"(c[1]), "+f"(c[2]), "+f"(c[3])
        : "r"(a[0]), "r"(a[1]), "r"(a[2]), "r"(a[3]), "r"(b0), "r"(b1));
}
__device__ __forceinline__ void ldsm4(uint32_t& r0, uint32_t& r1, uint32_t& r2, uint32_t& r3,
                                      uint32_t addr) {
    asm volatile("ldmatrix.sync.aligned.m8n8.x4.shared.b16 {%0,%1,%2,%3}, [%4];"
                 : "=r"(r0), "=r"(r1), "=r"(r2), "=r"(r3) : "r"(addr));
}
__device__ __forceinline__ float ex2(float x) {
    float r;
    asm("ex2.approx.f32 %0, %1;" : "=f"(r) : "f"(x));
    return r;
}
__device__ __forceinline__ uint32_t packh2(float a, float b) {
    __half2 t = __floats2half2_rn(a, b);
    return *reinterpret_cast<uint32_t*>(&t);
}

#define QSCALE 0.180337f        /* 0.125 * log2(e) */
#define SHIFT  (-4.32808512f)   /* -3 * log2(e)    */

// ---------------------------------------------------------------------------
// Kernel A: fused QKV projection on fp16 mma. grid (S/128, H, B), 128 thr.
// SMEM halves: xh[128*72] | wh[3][64*72] | vst[64*136]
// ---------------------------------------------------------------------------
#define XST 72
#define VST 136
#define QK_OFF_X 0
#define QK_OFF_W (128 * XST)
#define QK_OFF_VS (QK_OFF_W + 3 * 64 * XST)
#define QK_SMEM_HALVES (QK_OFF_VS + 64 * VST)

__global__ __launch_bounds__(128, 2) void qkv_kernel(
    const float* __restrict__ x,
    const float* __restrict__ Wq, const float* __restrict__ bq,
    const float* __restrict__ Wk, const float* __restrict__ bk,
    const float* __restrict__ Wv, const float* __restrict__ bv)
{
    extern __shared__ __half smh[];
    __half* xh  = smh + QK_OFF_X;
    __half* vst = smh + QK_OFF_VS;

    const int s0  = blockIdx.x * 128;
    const int h   = blockIdx.y;
    const int b   = blockIdx.z;
    const int tid = threadIdx.x;
    const int wid = tid >> 5;
    const int lane = tid & 31;
    const int g   = lane >> 2;
    const int tq  = lane & 3;
    const size_t bh = (size_t)b * Hsz + h;

    // load x tile [128 rows x 64 d] fp32 -> fp16 smem (stride 72)
    {
        const float4* xg = reinterpret_cast<const float4*>(x)
                         + ((size_t)(b * Ssz + s0) * Dsz + h * DHsz) / 4;
        #pragma unroll
        for (int i = 0; i < 16; i++) {
            int idx = tid + i * 128;
            int r = idx >> 4, c = idx & 15;
            float4 v = xg[r * (Dsz / 4) + c];
            __half2* d = reinterpret_cast<__half2*>(xh + r * XST + c * 4);
            d[0] = __floats2half2_rn(v.x, v.y);
            d[1] = __floats2half2_rn(v.z, v.w);
        }
    }
    const float* Ws[3] = {Wq, Wk, Wv};
    #pragma unroll
    for (int m = 0; m < 3; m++) {
        const float4* wg = reinterpret_cast<const float4*>(Ws[m] + (size_t)h * DHsz * DHsz);
        __half* wh = smh + QK_OFF_W + m * 64 * XST;
        #pragma unroll
        for (int i = 0; i < 8; i++) {
            int idx = tid + i * 128;
            int r = idx >> 4, c = idx & 15;
            float4 v = wg[idx];
            __half2* d = reinterpret_cast<__half2*>(wh + r * XST + c * 4);
            d[0] = __floats2half2_rn(v.x, v.y);
            d[1] = __floats2half2_rn(v.z, v.w);
        }
    }
    __syncthreads();

    uint32_t ax[2][4][4];
    {
        const __half* xw = xh + (wid * 32) * XST;
        #pragma unroll
        for (int m = 0; m < 2; m++)
            #pragma unroll
            for (int kc = 0; kc < 4; kc++) {
                const __half* r0 = xw + (m * 16 + g) * XST + 16 * kc + 2 * tq;
                ax[m][kc][0] = *(const uint32_t*)(r0);
                ax[m][kc][1] = *(const uint32_t*)(r0 + 8 * XST);
                ax[m][kc][2] = *(const uint32_t*)(r0 + 8);
                ax[m][kc][3] = *(const uint32_t*)(r0 + 8 * XST + 8);
            }
    }

    const float* bvec[3] = {bq, bk, bv};
    #pragma unroll
    for (int mm = 0; mm < 3; mm++) {
        const __half* wh = smh + QK_OFF_W + mm * 64 * XST;
        float sc[2][8][4];
        #pragma unroll
        for (int vn = 0; vn < 8; vn++) {
            float2 bb = *reinterpret_cast<const float2*>(
                bvec[mm] + h * DHsz + 8 * vn + 2 * tq);
            #pragma unroll
            for (int m = 0; m < 2; m++) {
                sc[m][vn][0] = bb.x; sc[m][vn][1] = bb.y;
                sc[m][vn][2] = bb.x; sc[m][vn][3] = bb.y;
            }
        }
        #pragma unroll
        for (int vn = 0; vn < 8; vn++) {
            const __half* wrow = wh + (8 * vn + g) * XST;
            #pragma unroll
            for (int kc = 0; kc < 4; kc++) {
                uint32_t b0 = *(const uint32_t*)(wrow + 16 * kc + 2 * tq);
                uint32_t b1 = *(const uint32_t*)(wrow + 16 * kc + 2 * tq + 8);
                mma_f16(sc[0][vn], ax[0][kc], b0, b1);
                mma_f16(sc[1][vn], ax[1][kc], b0, b1);
            }
        }

        if (mm < 2) {
            __half* O = (mm == 0 ? g_Qh : g_Kh) + (bh * Ssz + s0 + wid * 32) * DHsz;
            const float scl = (mm == 0) ? QSCALE : 1.0f;
            #pragma unroll
            for (int m = 0; m < 2; m++)
                #pragma unroll
                for (int vn = 0; vn < 8; vn++) {
                    int col = 8 * vn + 2 * tq;
                    *(uint32_t*)(O + (m * 16 + g) * DHsz + col) =
                        packh2(sc[m][vn][0] * scl, sc[m][vn][1] * scl);
                    *(uint32_t*)(O + (m * 16 + g + 8) * DHsz + col) =
                        packh2(sc[m][vn][2] * scl, sc[m][vn][3] * scl);
                }
        } else {
            #pragma unroll
            for (int m = 0; m < 2; m++)
                #pragma unroll
                for (int vn = 0; vn < 8; vn++) {
                    int e = 8 * vn + 2 * tq;
                    int s = wid * 32 + m * 16 + g;
                    vst[e * VST + s]           = __float2half_rn(sc[m][vn][0]);
                    vst[(e + 1) * VST + s]     = __float2half_rn(sc[m][vn][1]);
                    vst[e * VST + s + 8]       = __float2half_rn(sc[m][vn][2]);
                    vst[(e + 1) * VST + s + 8] = __float2half_rn(sc[m][vn][3]);
                }
            __syncthreads();
            #pragma unroll
            for (int i = 0; i < 8; i++) {
                int idx = tid + i * 128;
                int dh = idx >> 4, c = idx & 15;
                *reinterpret_cast<uint4*>(g_Vh + (bh * DHsz + dh) * Ssz + s0 + c * 8) =
                    *reinterpret_cast<const uint4*>(vst + dh * VST + c * 8);
            }
        }
    }
}

// ---------------------------------------------------------------------------
// Kernel B: FA2 attention, mma.sync m16n8k16 fp16, register P, ldmatrix B-frags,
// exp2-domain softmax (Q pre-scaled by log2e; shift -3*log2e in accumulator).
// grid (S/128, H, B), 128 threads, 2 CTAs/SM.
// SMEM halves: K[2][128*72] | V[2][64*136]
// ---------------------------------------------------------------------------
#define KSTh 72
#define VSTh 136
#define A_K_HALVES (128 * KSTh)
#define A_V_HALVES (64 * VSTh)
#define A_SMEM_HALVES (2 * A_K_HALVES + 2 * A_V_HALVES)

__global__ __launch_bounds__(128, 2) void attn_kernel(float* __restrict__ out)
{
    extern __shared__ __half smh[];

    const int tid  = threadIdx.x;
    const int wid  = tid >> 5;
    const int lane = tid & 31;
    const int g    = lane >> 2;
    const int tq   = lane & 3;
    const int l7   = lane & 7;
    const int lj   = lane >> 3;   // matrix index 0..3 within ldsm.x4

    const int q0 = blockIdx.x * 128;
    const int h  = blockIdx.y;
    const int b  = blockIdx.z;
    const size_t bh = (size_t)b * Hsz + h;

    const __half* Kg = g_Kh + bh * Ssz * DHsz;
    const __half* Vg = g_Vh + bh * DHsz * Ssz;

    const uint32_t sKa[2] = {smem_u32(smh), smem_u32(smh + A_K_HALVES)};
    const uint32_t sVa[2] = {smem_u32(smh + 2 * A_K_HALVES),
                             smem_u32(smh + 2 * A_K_HALVES + A_V_HALVES)};

    // ldmatrix lane offsets (in halves)
    const uint32_t kOff = (uint32_t)(l7 * KSTh + lj * 8);
    uint32_t vOff[4];
    #pragma unroll
    for (int q = 0; q < 4; q++)
        vOff[q] = (uint32_t)((16 * q + 8 * (lj >> 1) + l7) * VSTh + (lj & 1) * 8);

    // cp.async slots
    int krow[8], kch[8], vrow[8], vch[8];
    #pragma unroll
    for (int i = 0; i < 8; i++) {
        int idx = tid + i * 128;
        krow[i] = idx >> 3;  kch[i] = idx & 7;
        vrow[i] = idx >> 4;  vch[i] = idx & 15;
    }

    #pragma unroll
    for (int i = 0; i < 8; i++) {
        cpa16(sKa[0] + (krow[i] * KSTh + kch[i] * 8) * 2,
              Kg + (size_t)krow[i] * DHsz + kch[i] * 8);
        cpa16(sVa[0] + (vrow[i] * VSTh + vch[i] * 8) * 2,
              Vg + (size_t)vrow[i] * Ssz + vch[i] * 8);
    }
    asm volatile("cp.async.commit_group;" ::: "memory");

    uint32_t aq[2][4][4];
    {
        const __half* Qg = g_Qh + (bh * Ssz + q0 + wid * 32) * DHsz;
        #pragma unroll
        for (int m = 0; m < 2; m++)
            #pragma unroll
            for (int kc = 0; kc < 4; kc++) {
                const __half* r0 = Qg + (m * 16 + g) * DHsz + 16 * kc + 2 * tq;
                aq[m][kc][0] = *(const uint32_t*)(r0);
                aq[m][kc][1] = *(const uint32_t*)(r0 + 8 * DHsz);
                aq[m][kc][2] = *(const uint32_t*)(r0 + 8);
                aq[m][kc][3] = *(const uint32_t*)(r0 + 8 * DHsz + 8);
            }
    }

    float oc[2][8][4];
    #pragma unroll
    for (int m = 0; m < 2; m++)
        #pragma unroll
        for (int n = 0; n < 8; n++)
            #pragma unroll
            for (int i = 0; i < 4; i++) oc[m][n][i] = 0.f;
    float lsum[2][2] = {{0.f, 0.f}, {0.f, 0.f}};

    #pragma unroll 1
    for (int j = 0; j < 16; j++) {
        const int buf = j & 1;
        __syncthreads();
        if (j + 1 < 16) {
            const int nb = (j + 1) & 1;
            const int t0 = (j + 1) * 128;
            #pragma unroll
            for (int i = 0; i < 8; i++) {
                cpa16(sKa[nb] + (krow[i] * KSTh + kch[i] * 8) * 2,
                      Kg + (size_t)(t0 + krow[i]) * DHsz + kch[i] * 8);
                cpa16(sVa[nb] + (vrow[i] * VSTh + vch[i] * 8) * 2,
                      Vg + (size_t)vrow[i] * Ssz + t0 + vch[i] * 8);
            }
        }
        asm volatile("cp.async.commit_group;" ::: "memory");
        asm volatile("cp.async.wait_group 1;" ::: "memory");
        __syncthreads();

        const uint32_t kBase = sKa[buf] + kOff * 2;
        const uint32_t vBase = sVa[buf];

        #pragma unroll
        for (int u = 0; u < 8; u++) {
            float sc[2][2][4];
            #pragma unroll
            for (int p = 0; p < 2; p++)
                #pragma unroll
                for (int m = 0; m < 2; m++)
                    #pragma unroll
                    for (int i = 0; i < 4; i++) sc[p][m][i] = SHIFT;

            // GEMM1: per p, two ldsm.x4 cover k=0..31 and k=32..63
            #pragma unroll
            for (int p = 0; p < 2; p++) {
                uint32_t a0 = kBase + (uint32_t)((16 * u + 8 * p) * KSTh) * 2;
                uint32_t r0, r1, r2, r3;
                ldsm4(r0, r1, r2, r3, a0);
                mma_f16(sc[p][0], aq[0][0], r0, r1);
                mma_f16(sc[p][1], aq[1][0], r0, r1);
                mma_f16(sc[p][0], aq[0][1], r2, r3);
                mma_f16(sc[p][1], aq[1][1], r2, r3);
                ldsm4(r0, r1, r2, r3, a0 + 64);
                mma_f16(sc[p][0], aq[0][2], r0, r1);
                mma_f16(sc[p][1], aq[1][2], r0, r1);
                mma_f16(sc[p][0], aq[0][3], r2, r3);
                mma_f16(sc[p][1], aq[1][3], r2, r3);
            }

            // exp2 + pack: C-frags of (p=0, p=1) -> A-frag of k16 chunk u
            uint32_t pa[2][4];
            #pragma unroll
            for (int m = 0; m < 2; m++) {
                float f0 = ex2(sc[0][m][0]), f1 = ex2(sc[0][m][1]);
                float f2 = ex2(sc[0][m][2]), f3 = ex2(sc[0][m][3]);
                float h0 = ex2(sc[1][m][0]), h1 = ex2(sc[1][m][1]);
                float h2 = ex2(sc[1][m][2]), h3 = ex2(sc[1][m][3]);
                lsum[m][0] += (f0 + f1) + (h0 + h1);
                lsum[m][1] += (f2 + f3) + (h2 + h3);
                pa[m][0] = packh2(f0, f1);
                pa[m][1] = packh2(f2, f3);
                pa[m][2] = packh2(h0, h1);
                pa[m][3] = packh2(h2, h3);
            }

            // GEMM2: O += P[:, 16u:16u+16] @ V ; 4 ldsm.x4 cover vn pairs
            #pragma unroll
            for (int q = 0; q < 4; q++) {
                uint32_t av = vBase + (vOff[q] + (uint32_t)(16 * u)) * 2;
                uint32_t r0, r1, r2, r3;
                ldsm4(r0, r1, r2, r3, av);
                mma_f16(oc[0][2*q],   pa[0], r0, r1);
                mma_f16(oc[1][2*q],   pa[1], r0, r1);
                mma_f16(oc[0][2*q+1], pa[0], r2, r3);
                mma_f16(oc[1][2*q+1], pa[1], r2, r3);
            }
        }
    }

    float inv[2][2];
    #pragma unroll
    for (int m = 0; m < 2; m++)
        #pragma unroll
        for (int hh = 0; hh < 2; hh++) {
            float v = lsum[m][hh];
            v += __shfl_xor_sync(0xffffffff, v, 1);
            v += __shfl_xor_sync(0xffffffff, v, 2);
            inv[m][hh] = 1.f / v;
        }

    #pragma unroll
    for (int m = 0; m < 2; m++) {
        int r0 = q0 + wid * 32 + m * 16 + g;
        #pragma unroll
        for (int n = 0; n < 8; n++) {
            int col = h * DHsz + n * 8 + tq * 2;
            float2* p0 = reinterpret_cast<float2*>(out + (size_t)(b * Ssz + r0) * Dsz + col);
            float2* p1 = reinterpret_cast<float2*>(out + (size_t)(b * Ssz + r0 + 8) * Dsz + col);
            *p0 = make_float2(oc[m][n][0] * inv[m][0], oc[m][n][1] * inv[m][0]);
            *p1 = make_float2(oc[m][n][2] * inv[m][1], oc[m][n][3] * inv[m][1]);
        }
    }
}

extern "C" void kernel_launch(void* const* d_in, const int* in_sizes, int n_in,
                              void* d_out, int out_size)
{
    const float* seqs = (const float*)d_in[0];
    const float* Wq   = (const float*)d_in[1];
    const float* bq   = (const float*)d_in[2];
    const float* Wk   = (const float*)d_in[3];
    const float* bk   = (const float*)d_in[4];
    const float* Wv   = (const float*)d_in[5];
    const float* bv   = (const float*)d_in[6];
    float* out = (float*)d_out;

    cudaFuncSetAttribute(qkv_kernel, cudaFuncAttributeMaxDynamicSharedMemorySize,
                         QK_SMEM_HALVES * (int)sizeof(__half));
    cudaFuncSetAttribute(attn_kernel, cudaFuncAttributeMaxDynamicSharedMemorySize,
                         A_SMEM_HALVES * (int)sizeof(__half));

    dim3 gridQ(Ssz / 128, Hsz, Bsz);
    qkv_kernel<<<gridQ, 128, QK_SMEM_HALVES * sizeof(__half)>>>(
        seqs, Wq, bq, Wk, bk, Wv, bv);

    dim3 gridA(Ssz / 128, Hsz, Bsz);
    attn_kernel<<<gridA, 128, A_SMEM_HALVES * sizeof(__half)>>>(out);
}